// round 2
// baseline (speedup 1.0000x reference)
#include <cuda_runtime.h>
#include <cstdint>

#define SEQ    2048
#define BATCH  4
#define NHEADS 16
#define HDIM   64
#define DM     1024
#define BQ     128
#define BK     64
#define KSTR   68   // smem row stride for K tile (bank = 4g+t, conflict-free)
#define VSTR   72   // smem row stride for V tile (bank = 8t+g, conflict-free)

// Precomputed relative-bias table: [head][distance], distance = max(q-k, 0)
__device__ float g_bias[NHEADS * SEQ];

__global__ void build_bias_kernel(const float* __restrict__ rab) {
    int d = blockIdx.x * blockDim.x + threadIdx.x;
    if (d >= SEQ) return;
    int bkt;
    if (d < 16) {
        bkt = d;
    } else {
        // matches: 16 + int(log(d/16)/log(8) * 16), clamped to 31
        float t = logf((float)d * 0.0625f) / logf(8.0f) * 16.0f;
        bkt = 16 + (int)t;
        if (bkt > 31) bkt = 31;
    }
#pragma unroll
    for (int h = 0; h < NHEADS; ++h)
        g_bias[h * SEQ + d] = rab[bkt * NHEADS + h];
}

__device__ __forceinline__ unsigned f2tf(float x) {
    unsigned r;
    asm("cvt.rna.tf32.f32 %0, %1;" : "=r"(r) : "f"(x));
    return r;
}

__device__ __forceinline__ void mma_tf32(float c[4], const unsigned a[4],
                                         unsigned b0, unsigned b1) {
    asm volatile(
        "mma.sync.aligned.m16n8k8.row.col.f32.tf32.tf32.f32 "
        "{%0,%1,%2,%3}, {%4,%5,%6,%7}, {%8,%9}, {%0,%1,%2,%3};\n"
        : "+f"(c[0]), "+f"(c[1]), "+f"(c[2]), "+f"(c[3])
        : "r"(a[0]), "r"(a[1]), "r"(a[2]), "r"(a[3]), "r"(b0), "r"(b1));
}

__device__ __forceinline__ float silu(float s) {
    return s / (1.0f + __expf(-s));
}

__global__ void __launch_bounds__(128, 2) paa_kernel(
    const float* __restrict__ Q, const float* __restrict__ K,
    const float* __restrict__ V, float* __restrict__ Out)
{
    __shared__ float Ks[BK * KSTR];
    __shared__ float Vs[BK * VSTR];

    const int qt   = blockIdx.x;   // q tile (0..15)
    const int h    = blockIdx.y;   // head
    const int b    = blockIdx.z;   // batch
    const int tid  = threadIdx.x;
    const int warp = tid >> 5;
    const int lane = tid & 31;
    const int g    = lane >> 2;    // group id (row within mma tile)
    const int t    = lane & 3;     // thread in group

    const size_t headoff = (size_t)b * SEQ * DM + (size_t)h * HDIM;
    const float* qp = Q + headoff;
    const float* kp = K + headoff;
    const float* vp = V + headoff;
    const float* biasp = g_bias + h * SEQ;

    const int qrow0 = qt * BQ + warp * 32;  // this warp's first q row (2 m-tiles)

    // Preload Q fragments (tf32) for both m-tiles; register-resident for all k-tiles.
    unsigned qa[2][8][4];
#pragma unroll
    for (int m = 0; m < 2; ++m) {
        const int r = qrow0 + m * 16;
#pragma unroll
        for (int dc = 0; dc < 8; ++dc) {
            int c0 = dc * 8 + t;
            qa[m][dc][0] = f2tf(qp[(size_t)(r + g)     * DM + c0]);
            qa[m][dc][1] = f2tf(qp[(size_t)(r + g + 8) * DM + c0]);
            qa[m][dc][2] = f2tf(qp[(size_t)(r + g)     * DM + c0 + 4]);
            qa[m][dc][3] = f2tf(qp[(size_t)(r + g + 8) * DM + c0 + 4]);
        }
    }

    float oacc[2][8][4];
#pragma unroll
    for (int m = 0; m < 2; ++m)
#pragma unroll
        for (int i = 0; i < 8; ++i)
#pragma unroll
            for (int j = 0; j < 4; ++j) oacc[m][i][j] = 0.0f;

    for (int kt = 0; kt < SEQ / BK; ++kt) {
        const int k0 = kt * BK;
        __syncthreads();  // previous tile's reads finished
        // Cooperative load of K/V tiles (64x64), tf32-rounded at store time.
#pragma unroll
        for (int i = 0; i < 8; ++i) {
            int idx = tid + i * 128;     // 0..1023
            int row = idx >> 4;
            int cv  = (idx & 15) * 4;
            const float4 kf = *(const float4*)(kp + (size_t)(k0 + row) * DM + cv);
            const float4 vf = *(const float4*)(vp + (size_t)(k0 + row) * DM + cv);
            float4 ko, vo;
            ko.x = __uint_as_float(f2tf(kf.x)); ko.y = __uint_as_float(f2tf(kf.y));
            ko.z = __uint_as_float(f2tf(kf.z)); ko.w = __uint_as_float(f2tf(kf.w));
            vo.x = __uint_as_float(f2tf(vf.x)); vo.y = __uint_as_float(f2tf(vf.y));
            vo.z = __uint_as_float(f2tf(vf.z)); vo.w = __uint_as_float(f2tf(vf.w));
            *(float4*)(Ks + row * KSTR + cv) = ko;
            *(float4*)(Vs + row * VSTR + cv) = vo;
        }
        __syncthreads();

        // Process the 64 S-columns in two halves of 32 to cap live registers.
#pragma unroll
        for (int half = 0; half < 2; ++half) {
            // ---- S = Q @ K^T  (32 x 32 per warp, this half) ----
            float sacc[2][4][4];
#pragma unroll
            for (int m = 0; m < 2; ++m)
#pragma unroll
                for (int i = 0; i < 4; ++i)
#pragma unroll
                    for (int j = 0; j < 4; ++j) sacc[m][i][j] = 0.0f;

#pragma unroll
            for (int nc = 0; nc < 4; ++nc) {
                const float* krow = Ks + ((half * 4 + nc) * 8 + g) * KSTR;
#pragma unroll
                for (int dc = 0; dc < 8; ++dc) {
                    unsigned b0 = __float_as_uint(krow[dc * 8 + t]);
                    unsigned b1 = __float_as_uint(krow[dc * 8 + t + 4]);
                    mma_tf32(sacc[0][nc], qa[0][dc], b0, b1);
                    mma_tf32(sacc[1][nc], qa[1][dc], b0, b1);
                }
            }

            // ---- bias + silu + O += P @ V, chunk by chunk over k' ----
#pragma unroll
            for (int kc = 0; kc < 4; ++kc) {
                const int kcg = half * 4 + kc;        // global 8-col chunk index
                const int col0 = k0 + kcg * 8 + 2 * t;
                unsigned af[2][4];
#pragma unroll
                for (int m = 0; m < 2; ++m) {
                    const int r0 = qrow0 + m * 16 + g;
                    const int r1 = r0 + 8;
                    int d00 = r0 - col0;     if (d00 < 0) d00 = 0;
                    int d01 = r0 - col0 - 1; if (d01 < 0) d01 = 0;
                    int d10 = r1 - col0;     if (d10 < 0) d10 = 0;
                    int d11 = r1 - col0 - 1; if (d11 < 0) d11 = 0;
                    float s0 = sacc[m][kc][0] + biasp[d00];
                    float s1 = sacc[m][kc][1] + biasp[d01];
                    float s2 = sacc[m][kc][2] + biasp[d10];
                    float s3 = sacc[m][kc][3] + biasp[d11];
                    unsigned u0 = f2tf(silu(s0));
                    unsigned u1 = f2tf(silu(s1));
                    unsigned u2 = f2tf(silu(s2));
                    unsigned u3 = f2tf(silu(s3));

                    // Re-layout acc fragment (cols {2t,2t+1}) into A fragment
                    // (cols {t,t+4}) via intra-quad shuffles.
                    const int srcA = (lane & ~3) | (t >> 1);
                    const int srcB = srcA + 2;
                    unsigned sA0 = __shfl_sync(0xffffffffu, u0, srcA);
                    unsigned sA1 = __shfl_sync(0xffffffffu, u1, srcA);
                    unsigned sA2 = __shfl_sync(0xffffffffu, u2, srcA);
                    unsigned sA3 = __shfl_sync(0xffffffffu, u3, srcA);
                    unsigned sB0 = __shfl_sync(0xffffffffu, u0, srcB);
                    unsigned sB1 = __shfl_sync(0xffffffffu, u1, srcB);
                    unsigned sB2 = __shfl_sync(0xffffffffu, u2, srcB);
                    unsigned sB3 = __shfl_sync(0xffffffffu, u3, srcB);
                    af[m][0] = (t & 1) ? sA1 : sA0;  // (row g,   col t)
                    af[m][1] = (t & 1) ? sA3 : sA2;  // (row g+8, col t)
                    af[m][2] = (t & 1) ? sB1 : sB0;  // (row g,   col t+4)
                    af[m][3] = (t & 1) ? sB3 : sB2;  // (row g+8, col t+4)
                }

                const float* vrow0 = Vs + (kcg * 8 + t)     * VSTR + g;
                const float* vrow1 = Vs + (kcg * 8 + t + 4) * VSTR + g;
#pragma unroll
                for (int nc = 0; nc < 8; ++nc) {
                    unsigned b0 = __float_as_uint(vrow0[nc * 8]);
                    unsigned b1 = __float_as_uint(vrow1[nc * 8]);
                    mma_tf32(oacc[0][nc], af[0], b0, b1);
                    mma_tf32(oacc[1][nc], af[1], b0, b1);
                }
            }
        }
    }

    // ---- epilogue: O is [32 x 64] per warp, write to [B,S,H*64] ----
    float* op = Out + (size_t)b * SEQ * DM + (size_t)h * HDIM;
#pragma unroll
    for (int m = 0; m < 2; ++m) {
        const int r = qrow0 + m * 16;
#pragma unroll
        for (int nc = 0; nc < 8; ++nc) {
            int c = nc * 8 + 2 * t;
            float2 v01 = make_float2(oacc[m][nc][0], oacc[m][nc][1]);
            float2 v23 = make_float2(oacc[m][nc][2], oacc[m][nc][3]);
            *(float2*)(op + (size_t)(r + g)     * DM + c) = v01;
            *(float2*)(op + (size_t)(r + g + 8) * DM + c) = v23;
        }
    }
}

extern "C" void kernel_launch(void* const* d_in, const int* in_sizes, int n_in,
                              void* d_out, int out_size) {
    // metadata order: v, k, q, rab_weight
    const float* v   = (const float*)d_in[0];
    const float* k   = (const float*)d_in[1];
    const float* q   = (const float*)d_in[2];
    const float* rab = (const float*)d_in[3];
    float* out = (float*)d_out;

    build_bias_kernel<<<SEQ / 256, 256>>>(rab);

    dim3 grid(SEQ / BQ, NHEADS, BATCH);
    paa_kernel<<<grid, 128>>>(q, k, v, out);
}

// round 5
// speedup vs baseline: 1.1286x; 1.1286x over previous
#include <cuda_runtime.h>
#include <cstdint>

#define SEQ    2048
#define NHEADS 16
#define HDIM   64
#define DM     1024
#define BQ     64
#define BK     64
#define KSTR   72   // floats; LDS.64 pair-bank = 4g+t -> conflict-free
#define VSTR   72

// Precomputed relative-bias table: [head][distance], distance = max(q-k, 0)
__device__ float g_bias[NHEADS * SEQ];

__global__ void build_bias_kernel(const float* __restrict__ rab) {
    int d = blockIdx.x * blockDim.x + threadIdx.x;
    if (d >= SEQ) return;
    int bkt;
    if (d < 16) {
        bkt = d;
    } else {
        float t = logf((float)d * 0.0625f) / logf(8.0f) * 16.0f;
        bkt = 16 + (int)t;
        if (bkt > 31) bkt = 31;
    }
#pragma unroll
    for (int h = 0; h < NHEADS; ++h)
        g_bias[h * SEQ + d] = rab[bkt * NHEADS + h];
}

__device__ __forceinline__ unsigned f2tf(float x) {
    unsigned r;
    asm("cvt.rna.tf32.f32 %0, %1;" : "=r"(r) : "f"(x));
    return r;
}

__device__ __forceinline__ void mma_tf32(float c[4], const unsigned a[4],
                                         unsigned b0, unsigned b1) {
    asm volatile(
        "mma.sync.aligned.m16n8k8.row.col.f32.tf32.tf32.f32 "
        "{%0,%1,%2,%3}, {%4,%5,%6,%7}, {%8,%9}, {%0,%1,%2,%3};\n"
        : "+f"(c[0]), "+f"(c[1]), "+f"(c[2]), "+f"(c[3])
        : "r"(a[0]), "r"(a[1]), "r"(a[2]), "r"(a[3]), "r"(b0), "r"(b1));
}

// silu(x) = x * sigmoid(x) = x * (0.5*tanh(0.5x) + 0.5)   (1 MUFU)
__device__ __forceinline__ float silu(float s) {
    float th;
    asm("tanh.approx.f32 %0, %1;" : "=f"(th) : "f"(0.5f * s));
    return s * fmaf(0.5f, th, 0.5f);
}

__global__ void __launch_bounds__(128, 4) paa_kernel(
    const float* __restrict__ Q, const float* __restrict__ K,
    const float* __restrict__ V, float* __restrict__ Out)
{
    // K interleaved: element (r,d) at col' = (d&~7) | ((d&3)<<1) | ((d>>2)&1)
    // V transposed+interleaved: element (k,n) at row n, col k' (same interleave on k)
    __shared__ float Ks[BK * KSTR];
    __shared__ float Vt[HDIM * VSTR];
    __shared__ float Bs[SEQ];

    const int qt   = blockIdx.x;
    const int h    = blockIdx.y;
    const int b    = blockIdx.z;
    const int tid  = threadIdx.x;
    const int warp = tid >> 5;
    const int lane = tid & 31;
    const int g    = lane >> 2;
    const int t    = lane & 3;

    const size_t headoff = (size_t)b * SEQ * DM + (size_t)h * HDIM;
    const float* qp = Q + headoff;
    const float* kp = K + headoff;
    const float* vp = V + headoff;

    // bias row for this head -> smem
    const float* bg = g_bias + h * SEQ;
#pragma unroll
    for (int i = 0; i < 4; ++i) {
        int idx = (tid + 128 * i) * 4;
        *(float4*)(Bs + idx) = *(const float4*)(bg + idx);
    }

    const int qrow0 = qt * BQ + warp * 16;

    // Q fragments (tf32), register-resident.
    unsigned qa[8][4];
#pragma unroll
    for (int dc = 0; dc < 8; ++dc) {
        int c0 = dc * 8 + t;
        qa[dc][0] = f2tf(qp[(size_t)(qrow0 + g)     * DM + c0]);
        qa[dc][1] = f2tf(qp[(size_t)(qrow0 + g + 8) * DM + c0]);
        qa[dc][2] = f2tf(qp[(size_t)(qrow0 + g)     * DM + c0 + 4]);
        qa[dc][3] = f2tf(qp[(size_t)(qrow0 + g + 8) * DM + c0 + 4]);
    }

    float oacc[8][4];
#pragma unroll
    for (int i = 0; i < 8; ++i)
#pragma unroll
        for (int j = 0; j < 4; ++j) oacc[i][j] = 0.0f;

    const int srcA = (lane & ~3) | (t >> 1);
    const int srcB = srcA + 2;

    for (int kt = 0; kt < SEQ / BK; ++kt) {
        const int k0 = kt * BK;
        __syncthreads();  // previous tile's reads finished

        // ---- K tile: interleaved store, 8 floats per group ----
#pragma unroll
        for (int i = 0; i < 4; ++i) {
            int gidx = tid + 128 * i;          // 0..511
            int r = gidx >> 3, grp = gidx & 7;
            const float* src = kp + (size_t)(k0 + r) * DM + grp * 8;
            float4 A = *(const float4*)(src);
            float4 Bq = *(const float4*)(src + 4);
            uint4 u0, u1;
            u0.x = f2tf(A.x); u0.y = f2tf(Bq.x); u0.z = f2tf(A.y); u0.w = f2tf(Bq.y);
            u1.x = f2tf(A.z); u1.y = f2tf(Bq.z); u1.z = f2tf(A.w); u1.w = f2tf(Bq.w);
            float* dst = Ks + r * KSTR + grp * 8;
            *(uint4*)(dst)     = u0;
            *(uint4*)(dst + 4) = u1;
        }
        // ---- V tile: transpose + interleave on k ----
#pragma unroll
        for (int i = 0; i < 8; ++i) {
            int gidx = tid + 128 * i;          // 0..1023
            int kk = gidx & 63, n0 = (gidx >> 6) * 4;
            float4 vv = *(const float4*)(vp + (size_t)(k0 + kk) * DM + n0);
            int kq = (kk & ~7) | ((kk & 3) << 1) | ((kk >> 2) & 1);
            Vt[(n0 + 0) * VSTR + kq] = __uint_as_float(f2tf(vv.x));
            Vt[(n0 + 1) * VSTR + kq] = __uint_as_float(f2tf(vv.y));
            Vt[(n0 + 2) * VSTR + kq] = __uint_as_float(f2tf(vv.z));
            Vt[(n0 + 3) * VSTR + kq] = __uint_as_float(f2tf(vv.w));
        }
        __syncthreads();

        // ---- per 8-wide k-chunk: S-mma, epilogue, O-mma ----
#pragma unroll
        for (int nc = 0; nc < 8; ++nc) {
            float sacc[4] = {0.0f, 0.0f, 0.0f, 0.0f};
            const float* kbase = Ks + (nc * 8 + g) * KSTR + 2 * t;
#pragma unroll
            for (int dc = 0; dc < 8; ++dc) {
                float2 bb = *(const float2*)(kbase + dc * 8);
                mma_tf32(sacc, qa[dc], __float_as_uint(bb.x), __float_as_uint(bb.y));
            }

            // bias + silu
            const int col0 = k0 + nc * 8 + 2 * t;
            const int r0 = qrow0 + g;
            int d00 = r0 - col0;     if (d00 < 0) d00 = 0;
            int d01 = r0 - col0 - 1; if (d01 < 0) d01 = 0;
            int d10 = r0 + 8 - col0; if (d10 < 0) d10 = 0;
            int d11 = r0 + 7 - col0; if (d11 < 0) d11 = 0;
            float s0 = sacc[0] + Bs[d00];
            float s1 = sacc[1] + Bs[d01];
            float s2 = sacc[2] + Bs[d10];
            float s3 = sacc[3] + Bs[d11];
            unsigned u0 = f2tf(silu(s0));
            unsigned u1 = f2tf(silu(s1));
            unsigned u2 = f2tf(silu(s2));
            unsigned u3 = f2tf(silu(s3));

            // acc layout (cols {2t,2t+1}) -> A layout (cols {t,t+4}) via shuffles
            unsigned sA0 = __shfl_sync(0xffffffffu, u0, srcA);
            unsigned sA1 = __shfl_sync(0xffffffffu, u1, srcA);
            unsigned sA2 = __shfl_sync(0xffffffffu, u2, srcA);
            unsigned sA3 = __shfl_sync(0xffffffffu, u3, srcA);
            unsigned sB0 = __shfl_sync(0xffffffffu, u0, srcB);
            unsigned sB1 = __shfl_sync(0xffffffffu, u1, srcB);
            unsigned sB2 = __shfl_sync(0xffffffffu, u2, srcB);
            unsigned sB3 = __shfl_sync(0xffffffffu, u3, srcB);
            unsigned af[4];
            af[0] = (t & 1) ? sA1 : sA0;
            af[1] = (t & 1) ? sA3 : sA2;
            af[2] = (t & 1) ? sB1 : sB0;
            af[3] = (t & 1) ? sB3 : sB2;

            const float* vbase = Vt + g * VSTR + nc * 8 + 2 * t;
#pragma unroll
            for (int oc = 0; oc < 8; ++oc) {
                float2 vv = *(const float2*)(vbase + oc * 8 * VSTR);
                mma_tf32(oacc[oc], af, __float_as_uint(vv.x), __float_as_uint(vv.y));
            }
        }
    }

    // ---- epilogue ----
    float* op = Out + headoff + (size_t)qrow0 * DM;
#pragma unroll
    for (int oc = 0; oc < 8; ++oc) {
        int c = oc * 8 + 2 * t;
        *(float2*)(op + (size_t)g * DM + c)       = make_float2(oacc[oc][0], oacc[oc][1]);
        *(float2*)(op + (size_t)(g + 8) * DM + c) = make_float2(oacc[oc][2], oacc[oc][3]);
    }
}

extern "C" void kernel_launch(void* const* d_in, const int* in_sizes, int n_in,
                              void* d_out, int out_size) {
    // metadata order: v, k, q, rab_weight
    const float* v   = (const float*)d_in[0];
    const float* k   = (const float*)d_in[1];
    const float* q   = (const float*)d_in[2];
    const float* rab = (const float*)d_in[3];
    float* out = (float*)d_out;

    build_bias_kernel<<<SEQ / 256, 256>>>(rab);

    dim3 grid(SEQ / BQ, NHEADS, 4);
    paa_kernel<<<grid, 128>>>(q, k, v, out);
}

// round 6
// speedup vs baseline: 1.4645x; 1.2976x over previous
#include <cuda_runtime.h>
#include <cstdint>

#define SEQ    2048
#define NHEADS 16
#define HDIM   64
#define DM     1024
#define BQ     128
#define BK     64
#define KSTR   72   // floats; LDS.64 pair-bank = 4g+t per 16-lane phase -> conflict-free
#define VSTR   72

// Precomputed relative-bias table: [head][distance], distance = max(q-k, 0)
__device__ float g_bias[NHEADS * SEQ];

__global__ void build_bias_kernel(const float* __restrict__ rab) {
    int d = blockIdx.x * blockDim.x + threadIdx.x;
    if (d >= SEQ) return;
    int bkt;
    if (d < 16) {
        bkt = d;
    } else {
        float t = logf((float)d * 0.0625f) / logf(8.0f) * 16.0f;
        bkt = 16 + (int)t;
        if (bkt > 31) bkt = 31;
    }
#pragma unroll
    for (int h = 0; h < NHEADS; ++h)
        g_bias[h * SEQ + d] = rab[bkt * NHEADS + h];
}

__device__ __forceinline__ unsigned f2tf(float x) {
    unsigned r;
    asm("cvt.rna.tf32.f32 %0, %1;" : "=r"(r) : "f"(x));
    return r;
}

__device__ __forceinline__ void mma_tf32(float c[4], const unsigned a[4],
                                         unsigned b0, unsigned b1) {
    asm volatile(
        "mma.sync.aligned.m16n8k8.row.col.f32.tf32.tf32.f32 "
        "{%0,%1,%2,%3}, {%4,%5,%6,%7}, {%8,%9}, {%0,%1,%2,%3};\n"
        : "+f"(c[0]), "+f"(c[1]), "+f"(c[2]), "+f"(c[3])
        : "r"(a[0]), "r"(a[1]), "r"(a[2]), "r"(a[3]), "r"(b0), "r"(b1));
}

// silu(x) = x * sigmoid(x) = x * (0.5*tanh(0.5x) + 0.5)   (1 MUFU)
__device__ __forceinline__ float silu(float s) {
    float th;
    asm("tanh.approx.f32 %0, %1;" : "=f"(th) : "f"(0.5f * s));
    return s * fmaf(0.5f, th, 0.5f);
}

__global__ void __launch_bounds__(128, 3) paa_kernel(
    const float* __restrict__ Q, const float* __restrict__ K,
    const float* __restrict__ V, float* __restrict__ Out)
{
    // K interleaved: element (r,d) at col' = (d&~7) | ((d&3)<<1) | ((d>>2)&1)
    // V transposed+interleaved: element (k,n) at row n, col k' (same interleave on k)
    __shared__ float Ks[BK * KSTR];
    __shared__ float Vt[HDIM * VSTR];
    __shared__ float Bs[SEQ];

    const int qt   = blockIdx.x;
    const int h    = blockIdx.y;
    const int b    = blockIdx.z;
    const int tid  = threadIdx.x;
    const int warp = tid >> 5;
    const int lane = tid & 31;
    const int g    = lane >> 2;
    const int t    = lane & 3;

    const size_t headoff = (size_t)b * SEQ * DM + (size_t)h * HDIM;
    const float* qp = Q + headoff;
    const float* kp = K + headoff;
    const float* vp = V + headoff;

    // bias row for this head -> smem
    const float* bg = g_bias + h * SEQ;
#pragma unroll
    for (int i = 0; i < 4; ++i) {
        int idx = (tid + 128 * i) * 4;
        *(float4*)(Bs + idx) = *(const float4*)(bg + idx);
    }

    const int qrow0 = qt * BQ + warp * 32;  // two 16-row m-tiles per warp

    // Q fragments (tf32), register-resident for both m-tiles.
    unsigned qa[2][8][4];
#pragma unroll
    for (int m = 0; m < 2; ++m) {
        const int r = qrow0 + m * 16;
#pragma unroll
        for (int dc = 0; dc < 8; ++dc) {
            int c0 = dc * 8 + t;
            qa[m][dc][0] = f2tf(qp[(size_t)(r + g)     * DM + c0]);
            qa[m][dc][1] = f2tf(qp[(size_t)(r + g + 8) * DM + c0]);
            qa[m][dc][2] = f2tf(qp[(size_t)(r + g)     * DM + c0 + 4]);
            qa[m][dc][3] = f2tf(qp[(size_t)(r + g + 8) * DM + c0 + 4]);
        }
    }

    float oacc[2][8][4];
#pragma unroll
    for (int m = 0; m < 2; ++m)
#pragma unroll
        for (int i = 0; i < 8; ++i)
#pragma unroll
            for (int j = 0; j < 4; ++j) oacc[m][i][j] = 0.0f;

    const int srcA = (lane & ~3) | (t >> 1);
    const int srcB = srcA + 2;

    for (int kt = 0; kt < SEQ / BK; ++kt) {
        const int k0 = kt * BK;
        __syncthreads();  // previous tile's reads finished

        // ---- K tile: interleaved store ----
#pragma unroll
        for (int i = 0; i < 4; ++i) {
            int gidx = tid + 128 * i;          // 0..511
            int r = gidx >> 3, grp = gidx & 7;
            const float* src = kp + (size_t)(k0 + r) * DM + grp * 8;
            float4 A = *(const float4*)(src);
            float4 Bq = *(const float4*)(src + 4);
            uint4 u0, u1;
            u0.x = f2tf(A.x); u0.y = f2tf(Bq.x); u0.z = f2tf(A.y); u0.w = f2tf(Bq.y);
            u1.x = f2tf(A.z); u1.y = f2tf(Bq.z); u1.z = f2tf(A.w); u1.w = f2tf(Bq.w);
            float* dst = Ks + r * KSTR + grp * 8;
            *(uint4*)(dst)     = u0;
            *(uint4*)(dst + 4) = u1;
        }
        // ---- V tile: transpose + interleave on k ----
#pragma unroll
        for (int i = 0; i < 8; ++i) {
            int gidx = tid + 128 * i;          // 0..1023
            int kk = gidx & 63, n0 = (gidx >> 6) * 4;
            float4 vv = *(const float4*)(vp + (size_t)(k0 + kk) * DM + n0);
            int kq = (kk & ~7) | ((kk & 3) << 1) | ((kk >> 2) & 1);
            Vt[(n0 + 0) * VSTR + kq] = __uint_as_float(f2tf(vv.x));
            Vt[(n0 + 1) * VSTR + kq] = __uint_as_float(f2tf(vv.y));
            Vt[(n0 + 2) * VSTR + kq] = __uint_as_float(f2tf(vv.z));
            Vt[(n0 + 3) * VSTR + kq] = __uint_as_float(f2tf(vv.w));
        }
        __syncthreads();

        // ---- per 8-wide k-chunk: S-mma (both m), epilogue, O-mma (both m) ----
#pragma unroll
        for (int nc = 0; nc < 8; ++nc) {
            float sacc[2][4] = {{0.0f, 0.0f, 0.0f, 0.0f}, {0.0f, 0.0f, 0.0f, 0.0f}};
            const float* kbase = Ks + (nc * 8 + g) * KSTR + 2 * t;
#pragma unroll
            for (int dc = 0; dc < 8; ++dc) {
                float2 bb = *(const float2*)(kbase + dc * 8);
                unsigned b0 = __float_as_uint(bb.x), b1 = __float_as_uint(bb.y);
                mma_tf32(sacc[0], qa[0][dc], b0, b1);
                mma_tf32(sacc[1], qa[1][dc], b0, b1);
            }

            // bias + silu + relayout, per m-tile
            unsigned af[2][4];
            const int col0 = k0 + nc * 8 + 2 * t;
#pragma unroll
            for (int m = 0; m < 2; ++m) {
                const int r0 = qrow0 + m * 16 + g;
                int d00 = r0 - col0;     if (d00 < 0) d00 = 0;
                int d01 = r0 - col0 - 1; if (d01 < 0) d01 = 0;
                int d10 = r0 + 8 - col0; if (d10 < 0) d10 = 0;
                int d11 = r0 + 7 - col0; if (d11 < 0) d11 = 0;
                float s0 = sacc[m][0] + Bs[d00];
                float s1 = sacc[m][1] + Bs[d01];
                float s2 = sacc[m][2] + Bs[d10];
                float s3 = sacc[m][3] + Bs[d11];
                unsigned u0 = f2tf(silu(s0));
                unsigned u1 = f2tf(silu(s1));
                unsigned u2 = f2tf(silu(s2));
                unsigned u3 = f2tf(silu(s3));

                unsigned sA0 = __shfl_sync(0xffffffffu, u0, srcA);
                unsigned sA1 = __shfl_sync(0xffffffffu, u1, srcA);
                unsigned sA2 = __shfl_sync(0xffffffffu, u2, srcA);
                unsigned sA3 = __shfl_sync(0xffffffffu, u3, srcA);
                unsigned sB0 = __shfl_sync(0xffffffffu, u0, srcB);
                unsigned sB1 = __shfl_sync(0xffffffffu, u1, srcB);
                unsigned sB2 = __shfl_sync(0xffffffffu, u2, srcB);
                unsigned sB3 = __shfl_sync(0xffffffffu, u3, srcB);
                af[m][0] = (t & 1) ? sA1 : sA0;
                af[m][1] = (t & 1) ? sA3 : sA2;
                af[m][2] = (t & 1) ? sB1 : sB0;
                af[m][3] = (t & 1) ? sB3 : sB2;
            }

            const float* vbase = Vt + g * VSTR + nc * 8 + 2 * t;
#pragma unroll
            for (int oc = 0; oc < 8; ++oc) {
                float2 vv = *(const float2*)(vbase + oc * 8 * VSTR);
                unsigned b0 = __float_as_uint(vv.x), b1 = __float_as_uint(vv.y);
                mma_tf32(oacc[0][oc], af[0], b0, b1);
                mma_tf32(oacc[1][oc], af[1], b0, b1);
            }
        }
    }

    // ---- epilogue ----
#pragma unroll
    for (int m = 0; m < 2; ++m) {
        float* op = Out + headoff + (size_t)(qrow0 + m * 16) * DM;
#pragma unroll
        for (int oc = 0; oc < 8; ++oc) {
            int c = oc * 8 + 2 * t;
            *(float2*)(op + (size_t)g * DM + c)       = make_float2(oacc[m][oc][0], oacc[m][oc][1]);
            *(float2*)(op + (size_t)(g + 8) * DM + c) = make_float2(oacc[m][oc][2], oacc[m][oc][3]);
        }
    }
}

extern "C" void kernel_launch(void* const* d_in, const int* in_sizes, int n_in,
                              void* d_out, int out_size) {
    // metadata order: v, k, q, rab_weight
    const float* v   = (const float*)d_in[0];
    const float* k   = (const float*)d_in[1];
    const float* q   = (const float*)d_in[2];
    const float* rab = (const float*)d_in[3];
    float* out = (float*)d_out;

    build_bias_kernel<<<SEQ / 256, 256>>>(rab);

    dim3 grid(SEQ / BQ, NHEADS, 4);
    paa_kernel<<<grid, 128>>>(q, k, v, out);
}

// round 8
// speedup vs baseline: 1.7218x; 1.1757x over previous
#include <cuda_runtime.h>
#include <cuda_fp16.h>
#include <cstdint>

#define SEQ    2048
#define NHEADS 16
#define HDIM   64
#define DM     1024
#define BQ     128
#define BK     64
#define KSTR   72   // floats; LDS.64 pair-bank = 4g+t -> conflict-free
#define VSTRH  72   // halves;  LDS.32 bank = 4g+t (+4nc) -> conflict-free

// Precomputed relative-bias table: [head][distance], distance = max(q-k, 0)
__device__ float g_bias[NHEADS * SEQ];

__global__ void build_bias_kernel(const float* __restrict__ rab) {
    int d = blockIdx.x * blockDim.x + threadIdx.x;
    if (d >= SEQ) return;
    int bkt;
    if (d < 16) {
        bkt = d;
    } else {
        float t = logf((float)d * 0.0625f) / logf(8.0f) * 16.0f;
        bkt = 16 + (int)t;
        if (bkt > 31) bkt = 31;
    }
#pragma unroll
    for (int h = 0; h < NHEADS; ++h)
        g_bias[h * SEQ + d] = rab[bkt * NHEADS + h];
}

__device__ __forceinline__ unsigned f2tf(float x) {
    unsigned r;
    asm("cvt.rna.tf32.f32 %0, %1;" : "=r"(r) : "f"(x));
    return r;
}

// pack {lo, hi} floats into one half2 register ({lo in low half})
__device__ __forceinline__ unsigned pack_h2(float hi, float lo) {
    unsigned r;
    asm("cvt.rn.f16x2.f32 %0, %1, %2;" : "=r"(r) : "f"(hi), "f"(lo));
    return r;
}

__device__ __forceinline__ void mma_tf32(float c[4], const unsigned a[4],
                                         unsigned b0, unsigned b1) {
    asm volatile(
        "mma.sync.aligned.m16n8k8.row.col.f32.tf32.tf32.f32 "
        "{%0,%1,%2,%3}, {%4,%5,%6,%7}, {%8,%9}, {%0,%1,%2,%3};\n"
        : "+f"(c[0]), "+f"(c[1]), "+f"(c[2]), "+f"(c[3])
        : "r"(a[0]), "r"(a[1]), "r"(a[2]), "r"(a[3]), "r"(b0), "r"(b1));
}

__device__ __forceinline__ void mma_f16(float c[4], unsigned a0, unsigned a1,
                                        unsigned b0) {
    asm volatile(
        "mma.sync.aligned.m16n8k8.row.col.f32.f16.f16.f32 "
        "{%0,%1,%2,%3}, {%4,%5}, {%6}, {%0,%1,%2,%3};\n"
        : "+f"(c[0]), "+f"(c[1]), "+f"(c[2]), "+f"(c[3])
        : "r"(a0), "r"(a1), "r"(b0));
}

// silu(x) = x * sigmoid(x) = x * (0.5*tanh(0.5x) + 0.5)   (1 MUFU)
__device__ __forceinline__ float silu(float s) {
    float th;
    asm("tanh.approx.f32 %0, %1;" : "=f"(th) : "f"(0.5f * s));
    return s * fmaf(0.5f, th, 0.5f);
}

__global__ void __launch_bounds__(128, 3) paa_kernel(
    const float* __restrict__ Q, const float* __restrict__ K,
    const float* __restrict__ V, float* __restrict__ Out)
{
    // K interleaved tf32: element (r,d) at col' = (d&~7)|((d&3)<<1)|((d>>2)&1)
    // V transposed fp16: Vt[n][k] natural k order (half2 pairs adjacent)
    __shared__ float  Ks[BK * KSTR];
    __shared__ __half Vt[HDIM * VSTRH];
    __shared__ float  Bs[SEQ];

    const int qt   = blockIdx.x;
    const int h    = blockIdx.y;
    const int b    = blockIdx.z;
    const int tid  = threadIdx.x;
    const int warp = tid >> 5;
    const int lane = tid & 31;
    const int g    = lane >> 2;
    const int t    = lane & 3;

    const size_t headoff = (size_t)b * SEQ * DM + (size_t)h * HDIM;
    const float* qp = Q + headoff;
    const float* kp = K + headoff;
    const float* vp = V + headoff;

    // bias row for this head -> smem
    const float* bg = g_bias + h * SEQ;
#pragma unroll
    for (int i = 0; i < 4; ++i) {
        int idx = (tid + 128 * i) * 4;
        *(float4*)(Bs + idx) = *(const float4*)(bg + idx);
    }

    const int qrow0 = qt * BQ + warp * 32;  // two 16-row m-tiles per warp

    // Q fragments (tf32), register-resident for both m-tiles.
    unsigned qa[2][8][4];
#pragma unroll
    for (int m = 0; m < 2; ++m) {
        const int r = qrow0 + m * 16;
#pragma unroll
        for (int dc = 0; dc < 8; ++dc) {
            int c0 = dc * 8 + t;
            qa[m][dc][0] = f2tf(qp[(size_t)(r + g)     * DM + c0]);
            qa[m][dc][1] = f2tf(qp[(size_t)(r + g + 8) * DM + c0]);
            qa[m][dc][2] = f2tf(qp[(size_t)(r + g)     * DM + c0 + 4]);
            qa[m][dc][3] = f2tf(qp[(size_t)(r + g + 8) * DM + c0 + 4]);
        }
    }

    float oacc[2][8][4];
#pragma unroll
    for (int m = 0; m < 2; ++m)
#pragma unroll
        for (int i = 0; i < 8; ++i)
#pragma unroll
            for (int j = 0; j < 4; ++j) oacc[m][i][j] = 0.0f;

    for (int kt = 0; kt < SEQ / BK; ++kt) {
        const int k0 = kt * BK;
        __syncthreads();  // previous tile's reads finished

        // ---- K tile: interleaved tf32 store ----
#pragma unroll
        for (int i = 0; i < 4; ++i) {
            int gidx = tid + 128 * i;          // 0..511
            int r = gidx >> 3, grp = gidx & 7;
            const float* src = kp + (size_t)(k0 + r) * DM + grp * 8;
            float4 A = *(const float4*)(src);
            float4 Bq = *(const float4*)(src + 4);
            uint4 u0, u1;
            u0.x = f2tf(A.x); u0.y = f2tf(Bq.x); u0.z = f2tf(A.y); u0.w = f2tf(Bq.y);
            u1.x = f2tf(A.z); u1.y = f2tf(Bq.z); u1.z = f2tf(A.w); u1.w = f2tf(Bq.w);
            float* dst = Ks + r * KSTR + grp * 8;
            *(uint4*)(dst)     = u0;
            *(uint4*)(dst + 4) = u1;
        }
        // ---- V tile: transpose to fp16 Vt[n][k], natural k pairs ----
#pragma unroll
        for (int i = 0; i < 4; ++i) {
            int item = tid + 128 * i;          // 0..511
            int j  = item & 31;                // k-pair index (k = 2j, 2j+1)
            int ng = item >> 5;                // n-group (4 cols)
            const float* ra = vp + (size_t)(k0 + 2 * j) * DM + ng * 4;
            float4 va = *(const float4*)(ra);
            float4 vb = *(const float4*)(ra + DM);
            unsigned* dst = (unsigned*)Vt;
            dst[((ng * 4 + 0) * VSTRH + 2 * j) >> 1] = pack_h2(vb.x, va.x);
            dst[((ng * 4 + 1) * VSTRH + 2 * j) >> 1] = pack_h2(vb.y, va.y);
            dst[((ng * 4 + 2) * VSTRH + 2 * j) >> 1] = pack_h2(vb.z, va.z);
            dst[((ng * 4 + 3) * VSTRH + 2 * j) >> 1] = pack_h2(vb.w, va.w);
        }
        __syncthreads();

        // ---- per 8-wide k-chunk: S-mma (both m), silu+pack, O-mma (both m) ----
#pragma unroll
        for (int nc = 0; nc < 8; ++nc) {
            float sacc[2][4] = {{0.0f, 0.0f, 0.0f, 0.0f}, {0.0f, 0.0f, 0.0f, 0.0f}};
            const float* kbase = Ks + (nc * 8 + g) * KSTR + 2 * t;
#pragma unroll
            for (int dc = 0; dc < 8; ++dc) {
                float2 bb = *(const float2*)(kbase + dc * 8);
                unsigned b0 = __float_as_uint(bb.x), b1 = __float_as_uint(bb.y);
                mma_tf32(sacc[0], qa[0][dc], b0, b1);
                mma_tf32(sacc[1], qa[1][dc], b0, b1);
            }

            // bias + silu + pack to fp16 A fragments (no shuffles!)
            unsigned af[2][2];
            const int col0 = k0 + nc * 8 + 2 * t;
#pragma unroll
            for (int m = 0; m < 2; ++m) {
                const int r0 = qrow0 + m * 16 + g;
                int d00 = r0 - col0;     if (d00 < 0) d00 = 0;
                int d01 = r0 - col0 - 1; if (d01 < 0) d01 = 0;
                int d10 = r0 + 8 - col0; if (d10 < 0) d10 = 0;
                int d11 = r0 + 7 - col0; if (d11 < 0) d11 = 0;
                float p0 = silu(sacc[m][0] + Bs[d00]);
                float p1 = silu(sacc[m][1] + Bs[d01]);
                float p2 = silu(sacc[m][2] + Bs[d10]);
                float p3 = silu(sacc[m][3] + Bs[d11]);
                af[m][0] = pack_h2(p1, p0);   // {A[g][2t], A[g][2t+1]}
                af[m][1] = pack_h2(p3, p2);   // {A[g+8][2t], A[g+8][2t+1]}
            }

            const unsigned* vbase =
                (const unsigned*)Vt + ((g * VSTRH + nc * 8 + 2 * t) >> 1);
#pragma unroll
            for (int oc = 0; oc < 8; ++oc) {
                unsigned bv = vbase[oc * 8 * VSTRH / 2];
                mma_f16(oacc[0][oc], af[0][0], af[0][1], bv);
                mma_f16(oacc[1][oc], af[1][0], af[1][1], bv);
            }
        }
    }

    // ---- epilogue ----
#pragma unroll
    for (int m = 0; m < 2; ++m) {
        float* op = Out + headoff + (size_t)(qrow0 + m * 16) * DM;
#pragma unroll
        for (int oc = 0; oc < 8; ++oc) {
            int c = oc * 8 + 2 * t;
            *(float2*)(op + (size_t)g * DM + c)       = make_float2(oacc[m][oc][0], oacc[m][oc][1]);
            *(float2*)(op + (size_t)(g + 8) * DM + c) = make_float2(oacc[m][oc][2], oacc[m][oc][3]);
        }
    }
}

extern "C" void kernel_launch(void* const* d_in, const int* in_sizes, int n_in,
                              void* d_out, int out_size) {
    // metadata order: v, k, q, rab_weight
    const float* v   = (const float*)d_in[0];
    const float* k   = (const float*)d_in[1];
    const float* q   = (const float*)d_in[2];
    const float* rab = (const float*)d_in[3];
    float* out = (float*)d_out;

    build_bias_kernel<<<SEQ / 256, 256>>>(rab);

    dim3 grid(SEQ / BQ, NHEADS, 4);
    paa_kernel<<<grid, 128>>>(q, k, v, out);
}